// round 1
// baseline (speedup 1.0000x reference)
#include <cuda_runtime.h>

#define NR 512
#define DD 768
#define EPSF 1e-8f
#define LN2F 0.69314718055994530942f
#define LAMBDF 1.0f

#define TI 16
#define TJ 16
#define BK 256
#define PADF 260            // 256 + 4 floats padding -> conflict-free LDS.128
#define PAD4 (PADF/4)       // 65 float4 stride

// Scratch (no cudaMalloc allowed)
__device__ float  g_P1[NR * DD];   // p1 + eps
__device__ float  g_P2[NR * DD];   // p2 + eps
__device__ float  g_H1[NR];        // sum p1*ln(p1+eps)
__device__ float  g_H2[NR];
__device__ double g_tot;
__device__ double g_dia;

__global__ void zero_kernel() {
    g_tot = 0.0;
    g_dia = 0.0;
}

// One block per row; blocks [0,512) -> z1, [512,1024) -> z2. 256 threads, 3 elems each.
__global__ void softmax_kernel(const float* __restrict__ z1,
                               const float* __restrict__ z2) {
    const int  row   = blockIdx.x & (NR - 1);
    const bool first = blockIdx.x < NR;
    const float* src = (first ? z1 : z2) + row * DD;
    float*       dst = (first ? g_P1 : g_P2) + row * DD;
    float*      hrow = first ? g_H1 : g_H2;

    const int tid = threadIdx.x;
    const int w = tid >> 5, l = tid & 31;

    float x0 = src[tid];
    float x1 = src[tid + 256];
    float x2 = src[tid + 512];

    __shared__ float sred[8];

    // --- max reduce ---
    float mx = fmaxf(x0, fmaxf(x1, x2));
    #pragma unroll
    for (int o = 16; o; o >>= 1) mx = fmaxf(mx, __shfl_xor_sync(0xffffffffu, mx, o));
    if (l == 0) sred[w] = mx;
    __syncthreads();
    mx = sred[0];
    #pragma unroll
    for (int i = 1; i < 8; i++) mx = fmaxf(mx, sred[i]);
    __syncthreads();

    // --- exp + sum reduce ---
    float e0 = __expf(x0 - mx), e1 = __expf(x1 - mx), e2 = __expf(x2 - mx);
    float s = e0 + e1 + e2;
    #pragma unroll
    for (int o = 16; o; o >>= 1) s += __shfl_xor_sync(0xffffffffu, s, o);
    if (l == 0) sred[w] = s;
    __syncthreads();
    s = sred[0];
    #pragma unroll
    for (int i = 1; i < 8; i++) s += sred[i];
    __syncthreads();

    const float inv = 1.0f / s;
    float p0 = e0 * inv, p1 = e1 * inv, p2 = e2 * inv;
    float a0 = p0 + EPSF, a1 = p1 + EPSF, a2 = p2 + EPSF;
    dst[tid]       = a0;
    dst[tid + 256] = a1;
    dst[tid + 512] = a2;

    // --- H = sum p * ln(p+eps) ---
    float h = p0 * __log2f(a0) + p1 * __log2f(a1) + p2 * __log2f(a2);
    #pragma unroll
    for (int o = 16; o; o >>= 1) h += __shfl_xor_sync(0xffffffffu, h, o);
    if (l == 0) sred[w] = h;
    __syncthreads();
    if (tid == 0) {
        float hs = 0.f;
        #pragma unroll
        for (int i = 0; i < 8; i++) hs += sred[i];
        hrow[row] = hs * LN2F;
    }
}

// 16x16 pair tile per block, 256 threads, one (i,j) pair per thread.
// C(i,j) = ln2 * (T1 - 2eps*T2 - 2), with s = (p1+eps)+(p2+eps), u = log2(s),
// T1 = sum s*u, T2 = sum u. Inner loop: FADD + MUFU.LG2 + FFMA + FADD -> MUFU-bound.
__global__ void __launch_bounds__(256) pair_kernel() {
    __shared__ float As[TI * PADF];
    __shared__ float Bs[TJ * PADF];
    __shared__ float rtot[8], rdia[8];

    const int tid = threadIdx.x;
    const int ib = blockIdx.x & 31;   // 512/16 = 32 tiles per dim
    const int jb = blockIdx.x >> 5;
    const int ti = tid & 15;
    const int tj = tid >> 4;

    const float4* gp1 = (const float4*)(g_P1 + ib * TI * DD);
    const float4* gp2 = (const float4*)(g_P2 + jb * TJ * DD);

    float T1a = 0.f, T1b = 0.f, T2a = 0.f, T2b = 0.f;

    #pragma unroll 1
    for (int kb = 0; kb < 3; kb++) {
        // stage 16 x 256 chunk of each matrix (1024 float4 / 256 thr = 4 each)
        #pragma unroll
        for (int r = 0; r < 4; r++) {
            int idx = tid + r * 256;            // 0..1023
            int row = idx >> 6;                 // /64
            int c   = idx & 63;
            ((float4*)As)[row * PAD4 + c] = gp1[row * (DD / 4) + kb * (BK / 4) + c];
            ((float4*)Bs)[row * PAD4 + c] = gp2[row * (DD / 4) + kb * (BK / 4) + c];
        }
        __syncthreads();

        const float4* ar = (const float4*)(As + ti * PADF);
        const float4* br = (const float4*)(Bs + tj * PADF);

        #pragma unroll 8
        for (int k = 0; k < BK / 4; k += 2) {
            float4 a = ar[k],     b = br[k];
            float4 a2 = ar[k + 1], b2 = br[k + 1];

            float s0 = a.x + b.x;  float u0 = __log2f(s0);
            float s1 = a.y + b.y;  float u1 = __log2f(s1);
            float s2 = a.z + b.z;  float u2 = __log2f(s2);
            float s3 = a.w + b.w;  float u3 = __log2f(s3);
            T1a = fmaf(s0, u0, T1a); T2a += u0;
            T1a = fmaf(s1, u1, T1a); T2a += u1;
            T1a = fmaf(s2, u2, T1a); T2a += u2;
            T1a = fmaf(s3, u3, T1a); T2a += u3;

            float s4 = a2.x + b2.x;  float u4 = __log2f(s4);
            float s5 = a2.y + b2.y;  float u5 = __log2f(s5);
            float s6 = a2.z + b2.z;  float u6 = __log2f(s6);
            float s7 = a2.w + b2.w;  float u7 = __log2f(s7);
            T1b = fmaf(s4, u4, T1b); T2b += u4;
            T1b = fmaf(s5, u5, T1b); T2b += u5;
            T1b = fmaf(s6, u6, T1b); T2b += u6;
            T1b = fmaf(s7, u7, T1b); T2b += u7;
        }
        __syncthreads();
    }

    const float T1 = T1a + T1b;
    const float T2 = T2a + T2b;

    const int gi = ib * TI + ti;
    const int gj = jb * TJ + tj;

    // C = ln2*(T1 - 2eps*T2 - 2); jsd = 0.5*(H1 + H2 - C)
    float C   = LN2F * (T1 - 2.0f * EPSF * T2 - 2.0f);
    float jsd = 0.5f * (g_H1[gi] + g_H2[gj] - C);
    float dia = (gi == gj) ? jsd : 0.0f;

    float t = jsd, d = dia;
    #pragma unroll
    for (int o = 16; o; o >>= 1) {
        t += __shfl_xor_sync(0xffffffffu, t, o);
        d += __shfl_xor_sync(0xffffffffu, d, o);
    }
    const int w = tid >> 5, l = tid & 31;
    if (l == 0) { rtot[w] = t; rdia[w] = d; }
    __syncthreads();
    if (tid == 0) {
        float ts = 0.f, ds = 0.f;
        #pragma unroll
        for (int i = 0; i < 8; i++) { ts += rtot[i]; ds += rdia[i]; }
        atomicAdd(&g_tot, (double)ts);
        atomicAdd(&g_dia, (double)ds);
    }
}

__global__ void finalize_kernel(float* out) {
    double tot = g_tot, dia = g_dia;
    double pos = dia / (double)NR;
    double neg = -(tot - dia) / ((double)NR * NR - NR);
    out[0] = (float)(pos + (double)LAMBDF * neg);
}

extern "C" void kernel_launch(void* const* d_in, const int* in_sizes, int n_in,
                              void* d_out, int out_size) {
    const float* z1 = (const float*)d_in[0];
    const float* z2 = (const float*)d_in[1];
    float* out = (float*)d_out;

    zero_kernel<<<1, 1>>>();
    softmax_kernel<<<2 * NR, 256>>>(z1, z2);
    pair_kernel<<<(NR / TI) * (NR / TJ), 256>>>();
    finalize_kernel<<<1, 1>>>(out);
}